// round 9
// baseline (speedup 1.0000x reference)
#include <cuda_runtime.h>

// MeshfreeKANNet: u[m] = (sum_n phi_win[m,n]*w[n]) / (sum_n phi_win[m,n] + 1e-10)
// R8: the kernel was parallelism-starved (4096 warps vs 9472 slots -> occ
// ceiling 43%). Split each point's node range across SPLIT=4 warps (256 nodes
// each, ~18 hits -> 1 phase-2 iter), combine partials in smem. 16384 warps,
// multi-wave scheduling self-balances hit-count skew.
// Phase-2 body = R5 dense form (bit-exact reference math, LDS.128 weights).

#define MM      4096
#define NN      1024
#define HIDN    8
#define SPLIT   4                  // warps per point
#define WARPS   8                  // warps per block
#define PPB     (WARPS / SPLIT)    // points per block = 2
#define THREADS 256
#define BLOCKS  (MM / PPB)         // 2048
#define NQ      (NN / SPLIT)       // nodes per warp = 256

#define R2_F     0.09f
#define INV_R    (1.0f / 0.3f)
#define INV_H    (1.0f / 0.75f)

__global__ __launch_bounds__(THREADS, 5)
void meshfree_kan_kernel(const float* __restrict__ x,
                         const float* __restrict__ nodes,
                         const float* __restrict__ W1a,
                         const float* __restrict__ W1b,
                         const float* __restrict__ W2,
                         const float* __restrict__ w,
                         float* __restrict__ out)
{
    __shared__ float2 s_nxy[NN];
    __shared__ float  s_w[NN];
    // Packed weights: s_Wp[h] = {W1a[h][0..4], W1b[h][0..4], W2[h][0..4], 0}
    __shared__ float4 s_Wp[HIDN][4];
    __shared__ unsigned short s_buf[WARPS][NQ];
    __shared__ float  s_S[WARPS];
    __shared__ float  s_Sw[WARPS];

    const int tid = threadIdx.x;

    for (int i = tid; i < NN; i += THREADS) {
        s_nxy[i] = ((const float2*)nodes)[i];
        s_w[i]   = w[i];
    }
    if (tid < HIDN * 16) {
        const int h = tid >> 4;
        const int e = tid & 15;
        float v = 0.0f;
        if (e < 5)       v = W1a[h * 5 + e];
        else if (e < 10) v = W1b[h * 5 + (e - 5)];
        else if (e < 15) v = W2 [h * 5 + (e - 10)];
        ((float*)s_Wp)[tid] = v;
    }
    __syncthreads();

    const int warp = tid >> 5;
    const int lane = tid & 31;
    const int p    = warp / SPLIT;            // point within block (0..1)
    const int q    = warp & (SPLIT - 1);      // node-range quarter (0..3)
    const int m    = blockIdx.x * PPB + p;
    const int nq0  = q * NQ;

    const float px = x[2 * m];
    const float py = x[2 * m + 1];

    const float gridv[5] = {-1.5f, -0.75f, 0.0f, 0.75f, 1.5f};

    // ---- Phase 1: distance filter + warp stream compaction (own quarter) --
    int cnt = 0;
    const unsigned lmask = (1u << lane) - 1u;
    #pragma unroll
    for (int base = 0; base < NQ; base += 32) {
        const int n = nq0 + base + lane;
        const float2 nd = s_nxy[n];
        const float dx = px - nd.x;
        const float dy = py - nd.y;
        const float d2 = fmaf(dx, dx, dy * dy);
        const bool hit = (d2 <= R2_F);
        const unsigned msk = __ballot_sync(0xffffffffu, hit);
        if (hit) s_buf[warp][cnt + __popc(msk & lmask)] = (unsigned short)n;
        cnt += __popc(msk);
    }
    __syncwarp();

    // ---- Phase 2: dense KAN evaluation over compacted nodes ----
    float S = 0.0f, Sw = 0.0f;
    for (int i = lane; i < cnt; i += 32) {
        const int n = (int)s_buf[warp][i];
        const float2 nd = s_nxy[n];
        const float dx = px - nd.x;
        const float dy = py - nd.y;
        const float d2 = fmaf(dx, dx, dy * dy);
        const float kx = dx * INV_R;
        const float ky = dy * INV_R;

        // hat basis of the two KAN inputs (reference formulation, bit-exact)
        float ba[5], bb[5];
        #pragma unroll
        for (int s = 0; s < 5; s++) {
            ba[s] = fmaxf(0.0f, 1.0f - fabsf(kx - gridv[s]) * INV_H);
            bb[s] = fmaxf(0.0f, 1.0f - fabsf(ky - gridv[s]) * INV_H);
        }

        float phi_raw = 0.0f;
        #pragma unroll 2
        for (int h = 0; h < HIDN; h++) {
            const float4 q0 = s_Wp[h][0];
            const float4 q1 = s_Wp[h][1];
            const float4 q2 = s_Wp[h][2];
            const float4 q3 = s_Wp[h][3];
            const float wa[5]  = {q0.x, q0.y, q0.z, q0.w, q1.x};
            const float wb[5]  = {q1.y, q1.z, q1.w, q2.x, q2.y};
            const float w2r[5] = {q2.z, q2.w, q3.x, q3.y, q3.z};

            float hv = 0.0f;
            #pragma unroll
            for (int s = 0; s < 5; s++) {
                hv = fmaf(ba[s], wa[s], hv);
                hv = fmaf(bb[s], wb[s], hv);
            }
            #pragma unroll
            for (int s = 0; s < 5; s++) {
                const float bh = fmaxf(0.0f, 1.0f - fabsf(hv - gridv[s]) * INV_H);
                phi_raw = fmaf(bh, w2r[s], phi_raw);
            }
        }

        // cubic window: 1 - 6q^2 + 8q^3 - 3q^4
        const float qq = sqrtf(d2) * INV_R;
        const float win = fmaf(qq * qq, fmaf(fmaf(-3.0f, qq, 8.0f), qq, -6.0f), 1.0f);

        const float phi = phi_raw * win;
        S  += phi;
        Sw  = fmaf(phi, s_w[n], Sw);
    }

    // ---- Warp partial reduction ----
    #pragma unroll
    for (int o = 16; o > 0; o >>= 1) {
        S  += __shfl_xor_sync(0xffffffffu, S,  o);
        Sw += __shfl_xor_sync(0xffffffffu, Sw, o);
    }
    if (lane == 0) { s_S[warp] = S; s_Sw[warp] = Sw; }
    __syncthreads();

    // ---- Combine SPLIT partials per point (deterministic order) ----
    if (tid < PPB) {
        float St = 0.0f, Swt = 0.0f;
        #pragma unroll
        for (int qw = 0; qw < SPLIT; qw++) {
            St  += s_S [tid * SPLIT + qw];
            Swt += s_Sw[tid * SPLIT + qw];
        }
        out[blockIdx.x * PPB + tid] = Swt / (St + 1e-10f);
    }
}

extern "C" void kernel_launch(void* const* d_in, const int* in_sizes, int n_in,
                              void* d_out, int out_size)
{
    const float* x     = (const float*)d_in[0];   // [4096, 2]
    const float* nodes = (const float*)d_in[1];   // [1024, 2]
    const float* W1a   = (const float*)d_in[2];   // [8, 5]
    const float* W1b   = (const float*)d_in[3];   // [8, 5]
    const float* W2    = (const float*)d_in[4];   // [1, 40]
    const float* w     = (const float*)d_in[5];   // [1024, 1]
    float* out = (float*)d_out;                   // [4096, 1]

    meshfree_kan_kernel<<<BLOCKS, THREADS>>>(x, nodes, W1a, W1b, W2, w, out);
}

// round 10
// speedup vs baseline: 1.1131x; 1.1131x over previous
#include <cuda_runtime.h>

// MeshfreeKANNet: u[m] = (sum_n phi_win*w) / (sum_n phi_win + 1e-10), window
// support dist<=0.3 -> ~7% of pairs. R10:
//  * nodes/w read via __ldg (12KB working set lives in L1; no smem fill tax)
//  * block owns P=4 points; 8 warps compact half-ranges, segments relocated
//    into a flat pool of packed (p<<10|n) records; phase-2 warps stride the
//    pool statically -> ~100% lane utilization, deterministic.
//  * per-pair math bit-identical to the 14.6us R5 kernel; only summation
//    grouping differs (safe reordering).

#define MM      4096
#define NN      1024
#define HIDN    8
#define P       4                 // points per block
#define WARPS   8
#define THREADS 256
#define BLOCKS  (MM / P)          // 1024
#define NH      (NN / 2)          // nodes scanned per warp
#define SEGCAP  320               // >> max observed hits per half-range

#define R2_F     0.09f
#define INV_R    (1.0f / 0.3f)
#define INV_H    (1.0f / 0.75f)

__global__ __launch_bounds__(THREADS, 4)
void meshfree_kan_kernel(const float* __restrict__ x,
                         const float* __restrict__ nodes,
                         const float* __restrict__ W1a,
                         const float* __restrict__ W1b,
                         const float* __restrict__ W2,
                         const float* __restrict__ w,
                         float* __restrict__ out)
{
    __shared__ float4 s_Wp[HIDN][4];                  // {W1a[5],W1b[5],W2[5],0}
    __shared__ float2 s_pxy[P];
    __shared__ unsigned short s_seg[WARPS][SEGCAP];
    __shared__ unsigned short s_pool[WARPS * SEGCAP];
    __shared__ int   s_cnt[WARPS];
    __shared__ int   s_off[WARPS + 1];
    __shared__ float s_red[WARPS][2 * P];

    const int tid = threadIdx.x;
    const int m0  = blockIdx.x * P;

    if (tid < HIDN * 16) {
        const int h = tid >> 4;
        const int e = tid & 15;
        float v = 0.0f;
        if (e < 5)       v = W1a[h * 5 + e];
        else if (e < 10) v = W1b[h * 5 + (e - 5)];
        else if (e < 15) v = W2 [h * 5 + (e - 10)];
        ((float*)s_Wp)[tid] = v;
    }
    if (tid < P) s_pxy[tid] = ((const float2*)x)[m0 + tid];
    __syncthreads();

    const int warp = tid >> 5;
    const int lane = tid & 31;
    const int p    = warp >> 1;          // point within block
    const int half = warp & 1;           // node half-range
    const float2 pc = s_pxy[p];

    // ---- Phase 1: LDG scan + warp stream compaction into own segment ----
    int cnt = 0;
    const unsigned lmask = (1u << lane) - 1u;
    const int b0 = half * NH;
    #pragma unroll 4
    for (int base = b0; base < b0 + NH; base += 32) {
        const int n = base + lane;
        const float2 nd = __ldg((const float2*)nodes + n);
        const float dx = pc.x - nd.x;
        const float dy = pc.y - nd.y;
        const float d2 = fmaf(dx, dx, dy * dy);
        const bool hit = (d2 <= R2_F);
        const unsigned msk = __ballot_sync(0xffffffffu, hit);
        if (hit) s_seg[warp][cnt + __popc(msk & lmask)] = (unsigned short)n;
        cnt += __popc(msk);
    }
    if (lane == 0) s_cnt[warp] = cnt;
    __syncthreads();

    // ---- Offsets (tiny prefix over 8 counts) ----
    if (tid <= WARPS) {
        int o = 0;
        for (int i = 0; i < tid; i++) o += s_cnt[i];
        s_off[tid] = o;
    }
    __syncthreads();

    // ---- Relocate own segment into flat pool, packing (p<<10 | n) ----
    {
        const int o  = s_off[warp];
        const int pr = p << 10;
        for (int i = lane; i < cnt; i += 32)
            s_pool[o + i] = (unsigned short)(pr | (int)s_seg[warp][i]);
    }
    __syncthreads();

    const int T = s_off[WARPS];
    const float gridv[5] = {-1.5f, -0.75f, 0.0f, 0.75f, 1.5f};

    // ---- Phase 2: pooled KAN evaluation, static stride (deterministic) ----
    float S0 = 0.f, S1 = 0.f, S2 = 0.f, S3 = 0.f;
    float T0 = 0.f, T1 = 0.f, T2 = 0.f, T3 = 0.f;
    for (int j0 = warp * 32; j0 < T; j0 += THREADS) {
        const int j = j0 + lane;
        if (j < T) {
            const int rec = (int)s_pool[j];
            const int n   = rec & 1023;
            const int pp  = rec >> 10;
            const float2 pcp = s_pxy[pp];
            const float2 nd  = __ldg((const float2*)nodes + n);
            const float dx = pcp.x - nd.x;
            const float dy = pcp.y - nd.y;
            const float d2 = fmaf(dx, dx, dy * dy);
            const float kx = dx * INV_R;
            const float ky = dy * INV_R;

            float ba[5], bb[5];
            #pragma unroll
            for (int s = 0; s < 5; s++) {
                ba[s] = fmaxf(0.0f, 1.0f - fabsf(kx - gridv[s]) * INV_H);
                bb[s] = fmaxf(0.0f, 1.0f - fabsf(ky - gridv[s]) * INV_H);
            }

            float phi_raw = 0.0f;
            #pragma unroll 2
            for (int h = 0; h < HIDN; h++) {
                const float4 q0 = s_Wp[h][0];
                const float4 q1 = s_Wp[h][1];
                const float4 q2 = s_Wp[h][2];
                const float4 q3 = s_Wp[h][3];
                const float wa[5]  = {q0.x, q0.y, q0.z, q0.w, q1.x};
                const float wb[5]  = {q1.y, q1.z, q1.w, q2.x, q2.y};
                const float w2r[5] = {q2.z, q2.w, q3.x, q3.y, q3.z};

                float hv = 0.0f;
                #pragma unroll
                for (int s = 0; s < 5; s++) {
                    hv = fmaf(ba[s], wa[s], hv);
                    hv = fmaf(bb[s], wb[s], hv);
                }
                #pragma unroll
                for (int s = 0; s < 5; s++) {
                    const float bh = fmaxf(0.0f, 1.0f - fabsf(hv - gridv[s]) * INV_H);
                    phi_raw = fmaf(bh, w2r[s], phi_raw);
                }
            }

            const float qq  = sqrtf(d2) * INV_R;
            const float win = fmaf(qq * qq, fmaf(fmaf(-3.0f, qq, 8.0f), qq, -6.0f), 1.0f);
            const float phi = phi_raw * win;
            const float pw  = phi * __ldg(w + n);

            S0 += (pp == 0) ? phi : 0.0f;
            S1 += (pp == 1) ? phi : 0.0f;
            S2 += (pp == 2) ? phi : 0.0f;
            S3 += (pp == 3) ? phi : 0.0f;
            T0 += (pp == 0) ? pw  : 0.0f;
            T1 += (pp == 1) ? pw  : 0.0f;
            T2 += (pp == 2) ? pw  : 0.0f;
            T3 += (pp == 3) ? pw  : 0.0f;
        }
    }

    // ---- Per-warp reduction of the 8 partials ----
    #pragma unroll
    for (int o = 16; o > 0; o >>= 1) {
        S0 += __shfl_xor_sync(0xffffffffu, S0, o);
        S1 += __shfl_xor_sync(0xffffffffu, S1, o);
        S2 += __shfl_xor_sync(0xffffffffu, S2, o);
        S3 += __shfl_xor_sync(0xffffffffu, S3, o);
        T0 += __shfl_xor_sync(0xffffffffu, T0, o);
        T1 += __shfl_xor_sync(0xffffffffu, T1, o);
        T2 += __shfl_xor_sync(0xffffffffu, T2, o);
        T3 += __shfl_xor_sync(0xffffffffu, T3, o);
    }
    if (lane == 0) {
        s_red[warp][0] = S0; s_red[warp][1] = S1;
        s_red[warp][2] = S2; s_red[warp][3] = S3;
        s_red[warp][4] = T0; s_red[warp][5] = T1;
        s_red[warp][6] = T2; s_red[warp][7] = T3;
    }
    __syncthreads();

    // ---- Combine warp partials per point (fixed order -> deterministic) ----
    if (tid < P) {
        float St = 0.0f, Tt = 0.0f;
        #pragma unroll
        for (int wi = 0; wi < WARPS; wi++) {
            St += s_red[wi][tid];
            Tt += s_red[wi][4 + tid];
        }
        out[m0 + tid] = Tt / (St + 1e-10f);
    }
}

extern "C" void kernel_launch(void* const* d_in, const int* in_sizes, int n_in,
                              void* d_out, int out_size)
{
    const float* x     = (const float*)d_in[0];   // [4096, 2]
    const float* nodes = (const float*)d_in[1];   // [1024, 2]
    const float* W1a   = (const float*)d_in[2];   // [8, 5]
    const float* W1b   = (const float*)d_in[3];   // [8, 5]
    const float* W2    = (const float*)d_in[4];   // [1, 40]
    const float* w     = (const float*)d_in[5];   // [1024, 1]
    float* out = (float*)d_out;                   // [4096, 1]

    meshfree_kan_kernel<<<BLOCKS, THREADS>>>(x, nodes, W1a, W1b, W2, w, out);
}

// round 11
// speedup vs baseline: 1.2689x; 1.1400x over previous
#include <cuda_runtime.h>

// MeshfreeKANNet: u[m] = (sum_n phi_win[m,n]*w[n]) / (sum_n phi_win[m,n] + 1e-10)
// Warp per point; ballot-compaction of in-radius (~7%) nodes; dense KAN eval
// with packed LDS.128 weights (R5 = 14.6us baseline).
// R11: the binding constraint is the 40-deep serial phi_raw FMA chain per
// pair (~160 cyc) with too few warps to hide it. Unroll the hit loop by 2 so
// each lane runs TWO independent pair pipelines concurrently; S/Sw updated in
// the original order (A then B) -> bit-identical to R5.

#define MM      4096
#define NN      1024
#define HIDN    8
#define WARPS   8
#define THREADS 256
#define BLOCKS  (MM / WARPS)

#define R2_F     0.09f
#define INV_R    (1.0f / 0.3f)
#define INV_H    (1.0f / 0.75f)

typedef float4 f4;

// One pair's KAN evaluation. Bit-exact R5 math.
__device__ __forceinline__ float pair_phi(float dx, float dy,
                                          const f4 (*s_Wp)[4])
{
    const float gridv[5] = {-1.5f, -0.75f, 0.0f, 0.75f, 1.5f};
    const float d2 = fmaf(dx, dx, dy * dy);
    const float kx = dx * INV_R;
    const float ky = dy * INV_R;

    float ba[5], bb[5];
    #pragma unroll
    for (int s = 0; s < 5; s++) {
        ba[s] = fmaxf(0.0f, 1.0f - fabsf(kx - gridv[s]) * INV_H);
        bb[s] = fmaxf(0.0f, 1.0f - fabsf(ky - gridv[s]) * INV_H);
    }

    float phi_raw = 0.0f;
    #pragma unroll 2
    for (int h = 0; h < HIDN; h++) {
        const f4 q0 = s_Wp[h][0];
        const f4 q1 = s_Wp[h][1];
        const f4 q2 = s_Wp[h][2];
        const f4 q3 = s_Wp[h][3];
        const float wa[5]  = {q0.x, q0.y, q0.z, q0.w, q1.x};
        const float wb[5]  = {q1.y, q1.z, q1.w, q2.x, q2.y};
        const float w2r[5] = {q2.z, q2.w, q3.x, q3.y, q3.z};

        float hv = 0.0f;
        #pragma unroll
        for (int s = 0; s < 5; s++) {
            hv = fmaf(ba[s], wa[s], hv);
            hv = fmaf(bb[s], wb[s], hv);
        }
        #pragma unroll
        for (int s = 0; s < 5; s++) {
            const float bh = fmaxf(0.0f, 1.0f - fabsf(hv - gridv[s]) * INV_H);
            phi_raw = fmaf(bh, w2r[s], phi_raw);
        }
    }

    const float q = sqrtf(d2) * INV_R;
    const float win = fmaf(q * q, fmaf(fmaf(-3.0f, q, 8.0f), q, -6.0f), 1.0f);
    return phi_raw * win;
}

__global__ __launch_bounds__(THREADS, 4)
void meshfree_kan_kernel(const float* __restrict__ x,
                         const float* __restrict__ nodes,
                         const float* __restrict__ W1a,
                         const float* __restrict__ W1b,
                         const float* __restrict__ W2,
                         const float* __restrict__ w,
                         float* __restrict__ out)
{
    __shared__ float2 s_nxy[NN];
    __shared__ float  s_w[NN];
    __shared__ f4     s_Wp[HIDN][4];   // {W1a[h][0..4], W1b[h][0..4], W2[h][0..4], 0}
    __shared__ unsigned short s_buf[WARPS][NN];

    const int tid = threadIdx.x;

    for (int i = tid; i < NN; i += THREADS) {
        s_nxy[i] = ((const float2*)nodes)[i];
        s_w[i]   = w[i];
    }
    if (tid < HIDN * 16) {
        const int h = tid >> 4;
        const int e = tid & 15;
        float v = 0.0f;
        if (e < 5)       v = W1a[h * 5 + e];
        else if (e < 10) v = W1b[h * 5 + (e - 5)];
        else if (e < 15) v = W2 [h * 5 + (e - 10)];
        ((float*)s_Wp)[tid] = v;
    }
    __syncthreads();

    const int warp = tid >> 5;
    const int lane = tid & 31;
    const int m = blockIdx.x * WARPS + warp;

    const float px = x[2 * m];
    const float py = x[2 * m + 1];

    // ---- Phase 1: distance filter + warp stream compaction ----
    int cnt = 0;
    const unsigned lmask = (1u << lane) - 1u;
    #pragma unroll 4
    for (int base = 0; base < NN; base += 32) {
        const int n = base + lane;
        const float2 nd = s_nxy[n];
        const float dx = px - nd.x;
        const float dy = py - nd.y;
        const float d2 = fmaf(dx, dx, dy * dy);
        const bool hit = (d2 <= R2_F);
        const unsigned msk = __ballot_sync(0xffffffffu, hit);
        if (hit) s_buf[warp][cnt + __popc(msk & lmask)] = (unsigned short)n;
        cnt += __popc(msk);
    }
    __syncwarp();

    // ---- Phase 2: two independent pair pipelines per lane ----
    float S = 0.0f, Sw = 0.0f;
    for (int i = lane; i < cnt; i += 64) {
        const int iB = i + 32;
        const bool hasB = (iB < cnt);

        const int nA = (int)s_buf[warp][i];
        const float2 ndA = s_nxy[nA];
        const float phiA = pair_phi(px - ndA.x, py - ndA.y, s_Wp);

        float phiB = 0.0f;
        int nB = 0;
        if (hasB) {
            nB = (int)s_buf[warp][iB];
            const float2 ndB = s_nxy[nB];
            phiB = pair_phi(px - ndB.x, py - ndB.y, s_Wp);
        }

        // accumulate in original (i, then i+32) order -> bit-exact vs R5
        S  += phiA;
        Sw  = fmaf(phiA, s_w[nA], Sw);
        if (hasB) {
            S  += phiB;
            Sw  = fmaf(phiB, s_w[nB], Sw);
        }
    }

    // ---- Warp reduction + normalize ----
    #pragma unroll
    for (int o = 16; o > 0; o >>= 1) {
        S  += __shfl_xor_sync(0xffffffffu, S,  o);
        Sw += __shfl_xor_sync(0xffffffffu, Sw, o);
    }
    if (lane == 0) out[m] = Sw / (S + 1e-10f);
}

extern "C" void kernel_launch(void* const* d_in, const int* in_sizes, int n_in,
                              void* d_out, int out_size)
{
    const float* x     = (const float*)d_in[0];   // [4096, 2]
    const float* nodes = (const float*)d_in[1];   // [1024, 2]
    const float* W1a   = (const float*)d_in[2];   // [8, 5]
    const float* W1b   = (const float*)d_in[3];   // [8, 5]
    const float* W2    = (const float*)d_in[4];   // [1, 40]
    const float* w     = (const float*)d_in[5];   // [1024, 1]
    float* out = (float*)d_out;                   // [4096, 1]

    meshfree_kan_kernel<<<BLOCKS, THREADS>>>(x, nodes, W1a, W1b, W2, w, out);
}